// round 12
// baseline (speedup 1.0000x reference)
#include <cuda_runtime.h>
#include <cstdint>
#include <math.h>

#define T_TOK 8192
#define D_DIM 7168
#define E_EXP 256
#define K_TOP 8
#define G_GRP 8
#define LG_GRP 4

#define BM 128
#define BN 128
#define BK 16
#define NSTAGE (D_DIM / BK)   // 448

// smem rows: A duplicated {a,a}: 256 floats + 8 pad = 264 floats = 1056 B
//            B plain:            128 floats + 4 pad = 132 floats = 528 B
#define AROWB 1056
#define BROWB 528
#define A_BYTES (BK * AROWB)   // 16896
#define B_BYTES (BK * BROWB)   // 8448  -> total 25344 B, 1 CTA/SM

__device__ float g_logits[(size_t)T_TOK * E_EXP];
__device__ int   g_counts[E_EXP];

__device__ __forceinline__ uint32_t smem_to_u32(const void* p) {
    uint32_t a;
    asm("{ .reg .u64 t; cvta.to.shared.u64 t, %1; cvt.u32.u64 %0, t; }" : "=r"(a) : "l"(p));
    return a;
}

// packed f32x2 FMA: d += a * b
#define FFMA2(d, a, b) \
    asm("fma.rn.f32x2 %0, %1, %2, %0;" : "+l"(d) : "l"(a), "l"(b))

// 16B shared load as two packed-f32x2 operands
#define LDS_2U64(r0, r1, addr) \
    asm volatile("ld.shared.v2.u64 {%0, %1}, [%2];" : "=l"(r0), "=l"(r1) : "r"(addr))

// store duplicated float pair {v, v}
#define STS_DUP(addr, v) \
    asm volatile("st.shared.v2.f32 [%0], {%1, %1};" :: "r"(addr), "f"(v) : "memory")

#define STS_F32(addr, v) \
    asm volatile("st.shared.f32 [%0], %1;" :: "r"(addr), "f"(v) : "memory")

__device__ __forceinline__ float2 unpack2(uint64_t v) {
    uint32_t lo, hi;
    asm("mov.b64 {%0, %1}, %2;" : "=r"(lo), "=r"(hi) : "l"(v));
    float2 f; f.x = __uint_as_float(lo); f.y = __uint_as_float(hi);
    return f;
}

// ---------------- GEMM: C[t][e] = sum_k x[t][k] * W[e][k] ----------------
// R2's exact skeleton (256 thr, BK=16, single buffer, 2 syncs/stage, register
// prefetch); only operand plumbing changed: A duplicated in smem, B read as
// u64 pairs -> inner loop has ZERO pack MOVs (6 LDS + 32 FFMA2 per kk).
__global__ __launch_bounds__(256, 1)
void gemm_kernel(const float* __restrict__ A,   // x [T, D]
                 const float* __restrict__ B,   // W [E, D]
                 float* __restrict__ C)         // logits [T, E]
{
    __shared__ __align__(16) uint8_t smem[A_BYTES + B_BYTES];
    const uint32_t sa = smem_to_u32(smem);       // A-dup region
    const uint32_t sB = sa + A_BYTES;            // B region

    const int tid = threadIdx.x;
    const int tx = tid & 15;        // col group (8 cols each)
    const int ty = tid >> 4;        // row group (8 rows each)

    const float* Ab = A + (size_t)(blockIdx.y * BM) * D_DIM;
    const float* Bb = B + (size_t)(blockIdx.x * BN) * D_DIM;

    // loader mapping (identical to R2)
    const int lr = tid >> 2;          // 0..63
    const int lc = (tid & 3) * 4;     // 0,4,8,12

    // store bases
    const uint32_t a_st0 = sa + (uint32_t)lc * AROWB + (uint32_t)lr * 8u;          // rows 0..63 (dup)
    const uint32_t b_st0 = sB + (uint32_t)lc * BROWB + (uint32_t)lr * 4u;          // rows 0..63

    // compute-side bases
    const uint32_t a_lds = sa + (uint32_t)ty * 64u;    // 8 dup pairs = 64 B
    const uint32_t b_lds = sB + (uint32_t)tx * 32u;    // 8 cols = 32 B

    uint64_t acc[8][4];
    #pragma unroll
    for (int i = 0; i < 8; i++)
        #pragma unroll
        for (int j = 0; j < 4; j++) acc[i][j] = 0ull;

    // prefetch first tile (identical to R2)
    float4 a0 = *(const float4*)(Ab + (size_t)lr * D_DIM + lc);
    float4 a1 = *(const float4*)(Ab + (size_t)(lr + 64) * D_DIM + lc);
    float4 b0 = *(const float4*)(Bb + (size_t)lr * D_DIM + lc);
    float4 b1 = *(const float4*)(Bb + (size_t)(lr + 64) * D_DIM + lc);

    #pragma unroll 1
    for (int k0 = 0; k0 < D_DIM; k0 += BK) {
        __syncthreads();
        // store tile: A duplicated {v,v}, B scalar (k-major rows)
        {
            const float av0[4] = {a0.x, a0.y, a0.z, a0.w};
            const float av1[4] = {a1.x, a1.y, a1.z, a1.w};
            const float bv0[4] = {b0.x, b0.y, b0.z, b0.w};
            const float bv1[4] = {b1.x, b1.y, b1.z, b1.w};
            #pragma unroll
            for (int j = 0; j < 4; j++) {
                STS_DUP(a_st0 + (uint32_t)j * AROWB, av0[j]);
                STS_DUP(a_st0 + (uint32_t)j * AROWB + 512u, av1[j]);   // rows +64 -> +64*8 B
                STS_F32(b_st0 + (uint32_t)j * BROWB, bv0[j]);
                STS_F32(b_st0 + (uint32_t)j * BROWB + 256u, bv1[j]);   // rows +64 -> +64*4 B
            }
        }
        __syncthreads();

        // prefetch next tile (overlaps with compute below; identical to R2)
        const int kn = k0 + BK;
        if (kn < D_DIM) {
            a0 = *(const float4*)(Ab + (size_t)lr * D_DIM + kn + lc);
            a1 = *(const float4*)(Ab + (size_t)(lr + 64) * D_DIM + kn + lc);
            b0 = *(const float4*)(Bb + (size_t)lr * D_DIM + kn + lc);
            b1 = *(const float4*)(Bb + (size_t)(lr + 64) * D_DIM + kn + lc);
        }

        // compute: per kk, 6 LDS.128 + 32 FFMA2, zero MOVs
        #pragma unroll
        for (int kk = 0; kk < BK; kk++) {
            const uint32_t ka = a_lds + (uint32_t)kk * AROWB;
            const uint32_t kb = b_lds + (uint32_t)kk * BROWB;
            uint64_t a64[8], b64[4];
            LDS_2U64(a64[0], a64[1], ka);
            LDS_2U64(a64[2], a64[3], ka + 16u);
            LDS_2U64(a64[4], a64[5], ka + 32u);
            LDS_2U64(a64[6], a64[7], ka + 48u);
            LDS_2U64(b64[0], b64[1], kb);
            LDS_2U64(b64[2], b64[3], kb + 16u);
            #pragma unroll
            for (int i = 0; i < 8; i++)
                #pragma unroll
                for (int j = 0; j < 4; j++)
                    FFMA2(acc[i][j], a64[i], b64[j]);
        }
    }

    // epilogue (identical mapping to R2): rows ty*8+i, cols tx*8 + 2j
    const int row0 = blockIdx.y * BM + ty * 8;
    const int col0 = blockIdx.x * BN + tx * 8;
    #pragma unroll
    for (int i = 0; i < 8; i++) {
        float2 c0 = unpack2(acc[i][0]);
        float2 c1 = unpack2(acc[i][1]);
        float2 c2 = unpack2(acc[i][2]);
        float2 c3 = unpack2(acc[i][3]);
        float* cp = C + (size_t)(row0 + i) * E_EXP + col0;
        *(float4*)(cp)     = make_float4(c0.x, c0.y, c1.x, c1.y);
        *(float4*)(cp + 4) = make_float4(c2.x, c2.y, c3.x, c3.y);
    }
}

// ================= Routing: one warp per token (proven) =================
__global__ __launch_bounds__(256)
void route_kernel(const float* __restrict__ logits,
                  const float* __restrict__ bias,
                  void* __restrict__ w_out,
                  void* __restrict__ idx_out,
                  int mode)
{
    const float NEG_INF = __int_as_float(0xff800000);
    const int warp = threadIdx.x >> 5;
    const int lane = threadIdx.x & 31;
    const int t = blockIdx.x * 8 + warp;
    if (t >= T_TOK) return;

    const float* lp = logits + (size_t)t * E_EXP;

    float s[8], v[8];
    #pragma unroll
    for (int r = 0; r < 8; r++) {
        float z = __ldg(lp + r * 32 + lane);
        float sig = 1.0f / (1.0f + expf(-z));
        s[r] = sig;
        v[r] = sig + __ldg(bias + r * 32 + lane);
    }

    float gsc[8];
    #pragma unroll
    for (int r = 0; r < 8; r++) {
        float m1 = v[r], m2 = NEG_INF;
        #pragma unroll
        for (int off = 16; off; off >>= 1) {
            float o1 = __shfl_xor_sync(0xffffffffu, m1, off);
            float o2 = __shfl_xor_sync(0xffffffffu, m2, off);
            float hi = fmaxf(m1, o1);
            float lo = fminf(m1, o1);
            m2 = fmaxf(lo, fmaxf(m2, o2));
            m1 = hi;
        }
        gsc[r] = m1 + m2;
    }

    unsigned chosen = 0;
    #pragma unroll
    for (int it = 0; it < LG_GRP; it++) {
        float best = NEG_INF; int bg = 0;
        #pragma unroll
        for (int g = 0; g < G_GRP; g++) {
            bool free_g = ((chosen >> g) & 1u) == 0u;
            if (free_g && gsc[g] > best) { best = gsc[g]; bg = g; }
        }
        chosen |= 1u << bg;
    }
    #pragma unroll
    for (int r = 0; r < 8; r++)
        if (!((chosen >> r) & 1u)) v[r] = NEG_INF;

    float my_w = 0.0f;
    int   my_e = 0;
    #pragma unroll
    for (int k = 0; k < K_TOP; k++) {
        float lb = NEG_INF; int lr = 0;
        #pragma unroll
        for (int r = 0; r < 8; r++)
            if (v[r] > lb) { lb = v[r]; lr = r; }
        float bv = lb;
        int be = lr * 32 + lane;
        #pragma unroll
        for (int off = 16; off; off >>= 1) {
            float ov = __shfl_xor_sync(0xffffffffu, bv, off);
            int   oe = __shfl_xor_sync(0xffffffffu, be, off);
            if (ov > bv || (ov == bv && oe < be)) { bv = ov; be = oe; }
        }
        const int wr = be >> 5, wl = be & 31;
        float sv_sel = 0.0f;
        #pragma unroll
        for (int r = 0; r < 8; r++)
            if (r == wr) sv_sel = s[r];
        float ws = __shfl_sync(0xffffffffu, sv_sel, wl);
        if (lane == k) { my_w = ws; my_e = be; }
        if (lane == wl) {
            #pragma unroll
            for (int r = 0; r < 8; r++)
                if (r == wr) v[r] = NEG_INF;
        }
    }

    float wsum = (lane < K_TOP) ? my_w : 0.0f;
    #pragma unroll
    for (int off = 16; off; off >>= 1)
        wsum += __shfl_xor_sync(0xffffffffu, wsum, off);
    float wfin = my_w * (2.5f / wsum);

    if (lane < K_TOP) {
        const size_t o = (size_t)t * K_TOP + lane;
        if (mode == 2) {   // all-f32 concat (JAX promotion, x64 off)
            ((float*)w_out)[o]   = wfin;
            ((float*)idx_out)[o] = (float)my_e;
        } else {           // byte-concat f32 | i64 | i32
            ((float*)w_out)[o]       = wfin;
            ((long long*)idx_out)[o] = (long long)my_e;
        }
        atomicAdd(&g_counts[my_e], 1);
    }
}

__global__ void zero_counts_kernel() { g_counts[threadIdx.x] = 0; }

__global__ void write_counts_kernel(void* __restrict__ cnt_out, int mode) {
    const int e = threadIdx.x;
    if (mode == 2) ((float*)cnt_out)[e] = (float)g_counts[e];
    else           ((int*)cnt_out)[e]   = g_counts[e];
}

// ================= launch =================
extern "C" void kernel_launch(void* const* d_in, const int* in_sizes, int n_in,
                              void* d_out, int out_size)
{
    const float* x    = (const float*)d_in[0];
    const float* W    = (const float*)d_in[1];
    const float* bias = (const float*)d_in[2];

    char* base = (char*)d_out;
    const size_t TK = (size_t)T_TOK * K_TOP;

    int mode;
    void *w_out, *idx_out, *cnt_out;
    if (out_size == (int)(TK + TK + E_EXP)) {
        mode = 2;
        w_out   = base;
        idx_out = base + TK * 4;
        cnt_out = base + 2 * TK * 4;
    } else {
        mode = 0;
        w_out   = base;
        idx_out = base + TK * 4;
        cnt_out = base + TK * 4 + TK * 8;
    }

    zero_counts_kernel<<<1, E_EXP>>>();

    dim3 grid(E_EXP / BN, T_TOK / BM);   // (2, 64) = 128 CTAs
    gemm_kernel<<<grid, 256>>>(x, W, g_logits);

    route_kernel<<<T_TOK / 8, 256>>>(g_logits, bias, w_out, idx_out, mode);
    write_counts_kernel<<<1, E_EXP>>>(cnt_out, mode);
}

// round 13
// speedup vs baseline: 1.2416x; 1.2416x over previous
#include <cuda_runtime.h>
#include <cstdint>
#include <math.h>

#define T_TOK 8192
#define D_DIM 7168
#define E_EXP 256
#define K_TOP 8
#define G_GRP 8
#define LG_GRP 4

#define BM 128
#define BN 128
#define BK 16
#define PAD 132   // padded smem row (floats) to dodge bank conflicts

__device__ float g_logits[(size_t)T_TOK * E_EXP];

// ---------------- packed f32x2 helpers ----------------
__device__ __forceinline__ uint64_t pack2(float lo, float hi) {
    uint64_t r;
    asm("mov.b64 %0, {%1, %2};" : "=l"(r) : "r"(__float_as_uint(lo)), "r"(__float_as_uint(hi)));
    return r;
}
__device__ __forceinline__ void ffma2(uint64_t& d, uint64_t a, uint64_t b) {
    asm("fma.rn.f32x2 %0, %1, %2, %0;" : "+l"(d) : "l"(a), "l"(b));
}
__device__ __forceinline__ float2 unpack2(uint64_t v) {
    uint32_t lo, hi;
    asm("mov.b64 {%0, %1}, %2;" : "=r"(lo), "=r"(hi) : "l"(v));
    float2 f; f.x = __uint_as_float(lo); f.y = __uint_as_float(hi);
    return f;
}

// ---------------- GEMM: C[t][e] = sum_k x[t][k] * W[e][k] ----------------
// Byte-identical to the best-known (R2) kernel, plus: CTA (0,0) zeroes the
// output counts region at start (route launches only after this kernel ends).
__global__ __launch_bounds__(256, 1)
void gemm_kernel(const float* __restrict__ A,   // x [T, D]
                 const float* __restrict__ B,   // W [E, D]
                 float* __restrict__ C,         // logits [T, E]
                 void* __restrict__ cnt_out,
                 int mode)
{
    __shared__ float As[BK][PAD];
    __shared__ float Bs[BK][PAD];

    const int tid = threadIdx.x;

    // fold-in: zero the counts output region (one CTA, one store per thread)
    if (blockIdx.x == 0 && blockIdx.y == 0) {
        if (mode == 2) ((float*)cnt_out)[tid] = 0.0f;
        else           ((int*)cnt_out)[tid]   = 0;
    }

    const int tx = tid & 15;        // 0..15 -> col group (8 cols each)
    const int ty = tid >> 4;        // 0..15 -> row group (8 rows each)
    const int tile_n = blockIdx.x;  // 0..1   (E / BN)
    const int tile_m = blockIdx.y;  // 0..63  (T / BM)

    const float* Ab = A + (size_t)tile_m * BM * D_DIM;
    const float* Bb = B + (size_t)tile_n * BN * D_DIM;

    // global-load mapping: 2 rows x one float4 per thread, per matrix
    const int lr = tid >> 2;          // 0..63
    const int lc = (tid & 3) * 4;     // 0,4,8,12

    uint64_t acc[8][4];
    #pragma unroll
    for (int i = 0; i < 8; i++)
        #pragma unroll
        for (int j = 0; j < 4; j++) acc[i][j] = 0ull;

    // prefetch first tile
    float4 a0 = *(const float4*)(Ab + (size_t)lr * D_DIM + lc);
    float4 a1 = *(const float4*)(Ab + (size_t)(lr + 64) * D_DIM + lc);
    float4 b0 = *(const float4*)(Bb + (size_t)lr * D_DIM + lc);
    float4 b1 = *(const float4*)(Bb + (size_t)(lr + 64) * D_DIM + lc);

    for (int k0 = 0; k0 < D_DIM; k0 += BK) {
        __syncthreads();
        // transpose-store into smem: As[k][t], Bs[k][e]
        As[lc + 0][lr] = a0.x; As[lc + 1][lr] = a0.y; As[lc + 2][lr] = a0.z; As[lc + 3][lr] = a0.w;
        As[lc + 0][lr + 64] = a1.x; As[lc + 1][lr + 64] = a1.y; As[lc + 2][lr + 64] = a1.z; As[lc + 3][lr + 64] = a1.w;
        Bs[lc + 0][lr] = b0.x; Bs[lc + 1][lr] = b0.y; Bs[lc + 2][lr] = b0.z; Bs[lc + 3][lr] = b0.w;
        Bs[lc + 0][lr + 64] = b1.x; Bs[lc + 1][lr + 64] = b1.y; Bs[lc + 2][lr + 64] = b1.z; Bs[lc + 3][lr + 64] = b1.w;
        __syncthreads();

        // prefetch next tile (overlaps with compute below)
        const int kn = k0 + BK;
        if (kn < D_DIM) {
            a0 = *(const float4*)(Ab + (size_t)lr * D_DIM + kn + lc);
            a1 = *(const float4*)(Ab + (size_t)(lr + 64) * D_DIM + kn + lc);
            b0 = *(const float4*)(Bb + (size_t)lr * D_DIM + kn + lc);
            b1 = *(const float4*)(Bb + (size_t)(lr + 64) * D_DIM + kn + lc);
        }

        #pragma unroll
        for (int kk = 0; kk < BK; kk++) {
            float4 av0 = *(const float4*)&As[kk][ty * 8];
            float4 av1 = *(const float4*)&As[kk][ty * 8 + 4];
            float4 bv0 = *(const float4*)&Bs[kk][tx * 8];
            float4 bv1 = *(const float4*)&Bs[kk][tx * 8 + 4];
            uint64_t bp[4];
            bp[0] = pack2(bv0.x, bv0.y);
            bp[1] = pack2(bv0.z, bv0.w);
            bp[2] = pack2(bv1.x, bv1.y);
            bp[3] = pack2(bv1.z, bv1.w);
            float av[8] = {av0.x, av0.y, av0.z, av0.w, av1.x, av1.y, av1.z, av1.w};
            #pragma unroll
            for (int i = 0; i < 8; i++) {
                uint64_t ap = pack2(av[i], av[i]);
                #pragma unroll
                for (int j = 0; j < 4; j++) ffma2(acc[i][j], ap, bp[j]);
            }
        }
    }

    // epilogue: write 8x8 tile
    const int row0 = tile_m * BM + ty * 8;
    const int col0 = tile_n * BN + tx * 8;
    #pragma unroll
    for (int i = 0; i < 8; i++) {
        float2 c0 = unpack2(acc[i][0]);
        float2 c1 = unpack2(acc[i][1]);
        float2 c2 = unpack2(acc[i][2]);
        float2 c3 = unpack2(acc[i][3]);
        float4 v0 = make_float4(c0.x, c0.y, c1.x, c1.y);
        float4 v1 = make_float4(c2.x, c2.y, c3.x, c3.y);
        float* cp = C + (size_t)(row0 + i) * E_EXP + col0;
        *(float4*)(cp)     = v0;
        *(float4*)(cp + 4) = v1;
    }
}

// ---------------- Routing: one warp per token ----------------
// Writes weights + indices, and counts directly into the output buffer via
// atomics (float adds of 1.0f are exact up to 2^24 >> 65536).
__global__ __launch_bounds__(256)
void route_kernel(const float* __restrict__ logits,
                  const float* __restrict__ bias,
                  void* __restrict__ w_out,
                  void* __restrict__ idx_out,
                  void* __restrict__ cnt_out,
                  int mode)
{
    const float NEG_INF = __int_as_float(0xff800000);
    const int warp = threadIdx.x >> 5;
    const int lane = threadIdx.x & 31;
    const int t = blockIdx.x * 8 + warp;
    if (t >= T_TOK) return;

    const float* lp = logits + (size_t)t * E_EXP;

    float s[8];   // original sigmoid scores (used for weights)
    float v[8];   // biased scores (used for routing)
    #pragma unroll
    for (int r = 0; r < 8; r++) {
        float z = __ldg(lp + r * 32 + lane);
        float sig = 1.0f / (1.0f + expf(-z));
        s[r] = sig;
        v[r] = sig + __ldg(bias + r * 32 + lane);
    }

    // group scores: sum of top-2 biased scores per group (group r = reg r)
    float gsc[8];
    #pragma unroll
    for (int r = 0; r < 8; r++) {
        float m1 = v[r], m2 = NEG_INF;
        #pragma unroll
        for (int off = 16; off; off >>= 1) {
            float o1 = __shfl_xor_sync(0xffffffffu, m1, off);
            float o2 = __shfl_xor_sync(0xffffffffu, m2, off);
            float hi = fmaxf(m1, o1);
            float lo = fminf(m1, o1);
            m2 = fmaxf(lo, fmaxf(m2, o2));
            m1 = hi;
        }
        gsc[r] = m1 + m2;
    }

    // top-LG groups (ties -> lower group index, matching jax top_k)
    unsigned chosen = 0;
    #pragma unroll
    for (int it = 0; it < LG_GRP; it++) {
        float best = NEG_INF; int bg = 0;
        #pragma unroll
        for (int g = 0; g < G_GRP; g++) {
            bool free_g = ((chosen >> g) & 1u) == 0u;
            if (free_g && gsc[g] > best) { best = gsc[g]; bg = g; }
        }
        chosen |= 1u << bg;
    }
    #pragma unroll
    for (int r = 0; r < 8; r++)
        if (!((chosen >> r) & 1u)) v[r] = NEG_INF;

    // top-K experts, descending, ties -> lower expert index
    float my_w = 0.0f;
    int   my_e = 0;
    #pragma unroll
    for (int k = 0; k < K_TOP; k++) {
        float lb = NEG_INF; int lr = 0;
        #pragma unroll
        for (int r = 0; r < 8; r++)
            if (v[r] > lb) { lb = v[r]; lr = r; }
        float bv = lb;
        int be = lr * 32 + lane;
        #pragma unroll
        for (int off = 16; off; off >>= 1) {
            float ov = __shfl_xor_sync(0xffffffffu, bv, off);
            int   oe = __shfl_xor_sync(0xffffffffu, be, off);
            if (ov > bv || (ov == bv && oe < be)) { bv = ov; be = oe; }
        }
        const int wr = be >> 5, wl = be & 31;
        float sv_sel = 0.0f;
        #pragma unroll
        for (int r = 0; r < 8; r++)
            if (r == wr) sv_sel = s[r];
        float ws = __shfl_sync(0xffffffffu, sv_sel, wl);
        if (lane == k) { my_w = ws; my_e = be; }
        if (lane == wl) {
            #pragma unroll
            for (int r = 0; r < 8; r++)
                if (r == wr) v[r] = NEG_INF;
        }
    }

    // normalize: w = s / sum(s) * ROUTE_SCALE
    float wsum = (lane < K_TOP) ? my_w : 0.0f;
    #pragma unroll
    for (int off = 16; off; off >>= 1)
        wsum += __shfl_xor_sync(0xffffffffu, wsum, off);
    float wfin = my_w * (2.5f / wsum);

    if (lane < K_TOP) {
        const size_t o = (size_t)t * K_TOP + lane;
        if (mode == 2) {   // all-float32 concatenated layout
            ((float*)w_out)[o]   = wfin;
            ((float*)idx_out)[o] = (float)my_e;
            atomicAdd((float*)cnt_out + my_e, 1.0f);
        } else {           // byte-concatenated: f32 weights, i64 indices, i32 counts
            ((float*)w_out)[o]       = wfin;
            ((long long*)idx_out)[o] = (long long)my_e;
            atomicAdd((int*)cnt_out + my_e, 1);
        }
    }
}

// ---------------- launch ----------------
extern "C" void kernel_launch(void* const* d_in, const int* in_sizes, int n_in,
                              void* d_out, int out_size)
{
    const float* x    = (const float*)d_in[0];
    const float* W    = (const float*)d_in[1];
    const float* bias = (const float*)d_in[2];

    char* base = (char*)d_out;
    const size_t TK = (size_t)T_TOK * K_TOP;   // 65536

    int mode;
    void *w_out, *idx_out, *cnt_out;
    if (out_size == (int)(TK + TK + E_EXP)) {
        // 131328 elements: single-dtype f32 concat (JAX promotion, x64 off)
        mode = 2;
        w_out   = base;
        idx_out = base + TK * 4;
        cnt_out = base + 2 * TK * 4;
    } else {
        // byte-concatenated outputs: f32 weights | i64 indices | i32 counts
        mode = 0;
        w_out   = base;
        idx_out = base + TK * 4;
        cnt_out = base + TK * 4 + TK * 8;
    }

    dim3 grid(E_EXP / BN, T_TOK / BM);   // (2, 64) = 128 CTAs
    gemm_kernel<<<grid, 256>>>(x, W, g_logits, cnt_out, mode);

    route_kernel<<<T_TOK / 8, 256>>>(g_logits, bias, w_out, idx_out, cnt_out, mode);
}